// round 6
// baseline (speedup 1.0000x reference)
#include <cuda_runtime.h>
#include <cuda_fp16.h>

// NeRF volume-rendering aggregation — R6.
// R2/R4/R5 all pinned at ~35us = bytes/5.4TB/s: pure DRAM-achieved-BW bound,
// with DRAM only 68% busy -> demand gaps. Changes:
//  - PERSISTENT grid-stride kernel (148*8 blocks): removes ~6 wave transitions
//    (~2360 cyc each) and keeps every SM's load queue continuously fed.
//  - rgb algebra: accumulate sum(w*t) and fold sigma=0.5t+0.5 once per ray
//    after the tree-reduce (saves 12 FMA/lane, shorter tail).
// Layout unchanged from R5: lane owns 4 consecutive points, one warp scan,
// smem-staged transpose of raw, f16x2 tanh sigmoids, f32 exp for alpha.

#define FARV 1e10f
#define EPSV 1e-10f
#define FULL 0xffffffffu

__device__ __forceinline__ __half2 h2_tanh(__half2 x) {
    __half2 r;
    asm("tanh.approx.f16x2 %0, %1;" : "=r"(*(unsigned*)&r) : "r"(*(unsigned*)&x));
    return r;
}

// XOR-swizzle byte address within a 2048B tile: folds addr bits [8:7] into [5:4].
__device__ __forceinline__ unsigned swz(unsigned a) {
    return a ^ ((a >> 3) & 0x30u);
}

__global__ __launch_bounds__(256) void nerf_agg_kernel(
    const float4* __restrict__ raw,    // (NR, 128) of float4
    const float*  __restrict__ z,      // (NR, 128)
    const float*  __restrict__ rays_d, // (NR, 3)
    const float*  __restrict__ bg,     // (3)
    float* __restrict__ out_rgb,       // (NR, 3)
    float* __restrict__ out_depth,     // (NR)
    float* __restrict__ out_disp,      // (NR)
    float* __restrict__ out_alpha,     // (NR)
    float* __restrict__ out_w,         // (NR, 128)
    int nrays)
{
    __shared__ char sbuf[8 * 2048];    // per-warp 128-point float4 staging tile

    const int warp = threadIdx.x >> 5;
    const int lane = threadIdx.x & 31;
    char* sw = sbuf + warp * 2048;

    const int gw = blockIdx.x * 8 + warp;     // global warp id
    const int W  = gridDim.x * 8;             // total warps (stride)

    for (int ray = gw; ray < nrays; ray += W) {
        const float4* rawr = raw + (size_t)ray * 128;

        // ---- coalesced loads (front-batched, feeds DRAM queue) ----
        const float4 rv0 = rawr[lane];
        const float4 rv1 = rawr[32 + lane];
        const float4 rv2 = rawr[64 + lane];
        const float4 rv3 = rawr[96 + lane];
        const float4 z4  = *(const float4*)(z + (size_t)ray * 128 + lane * 4);

        const float dx = rays_d[ray * 3 + 0];
        const float dy = rays_d[ray * 3 + 1];
        const float dz = rays_d[ray * 3 + 2];
        const float nrm = sqrtf(dx * dx + dy * dy + dz * dz);

        // ---- transpose raw through SMEM ----
        __syncwarp();                          // prior iteration's reads done
        *(float4*)(sw + swz((lane      ) * 16u)) = rv0;
        *(float4*)(sw + swz((32 + lane ) * 16u)) = rv1;
        *(float4*)(sw + swz((64 + lane ) * 16u)) = rv2;
        *(float4*)(sw + swz((96 + lane ) * 16u)) = rv3;
        __syncwarp();
        float4 pt[4];
#pragma unroll
        for (int i = 0; i < 4; i++)
            pt[i] = *(const float4*)(sw + swz((lane * 4 + i) * 16u));

        // ---- z neighbors: lane-local except the lane boundary ----
        const float zn3 = __shfl_down_sync(FULL, z4.x, 1);   // z[lane*4+4]
        const float zloc[4] = { z4.x, z4.y, z4.z, z4.w };
        const float znxt[4] = { z4.y, z4.z, z4.w, zn3 };

        // ---- alpha + transmittance factors (f32 EX2) ----
        float alpha[4], t[4];
#pragma unroll
        for (int i = 0; i < 4; i++) {
            float d = znxt[i] - zloc[i];
            if (i == 3 && lane == 31) d = FARV;              // p == 127
            d *= nrm;
            const float ex = __expf(-fmaxf(pt[i].w, 0.0f) * d);
            alpha[i] = 1.0f - ex;
            t[i]     = ex + EPSV;                            // 1 - alpha + EPS
        }

        // ---- single warp scan over local products ----
        float S = (t[0] * t[1]) * (t[2] * t[3]);
#pragma unroll
        for (int off = 1; off < 32; off <<= 1) {
            const float v = __shfl_up_sync(FULL, S, off);
            S = (lane >= off) ? S * v : S;
        }
        float E = __shfl_up_sync(FULL, S, 1);                // exclusive lane prefix
        if (lane == 0) E = 1.0f;

        const float e1 = E  * t[0];
        const float e2 = e1 * t[1];
        const float e3 = e2 * t[2];
        const float w0 = alpha[0] * E;
        const float w1 = alpha[1] * e1;
        const float w2 = alpha[2] * e2;
        const float w3 = alpha[3] * e3;

        *(float4*)(out_w + (size_t)ray * 128 + lane * 4) = make_float4(w0, w1, w2, w3);

        // ---- packed tanh; accumulate RAW tanh dot-products (sigma folded later) ----
        const __half2 hx0 = h2_tanh(__floats2half2_rn(0.5f * pt[0].x, 0.5f * pt[1].x));
        const __half2 hy0 = h2_tanh(__floats2half2_rn(0.5f * pt[0].y, 0.5f * pt[1].y));
        const __half2 hz0 = h2_tanh(__floats2half2_rn(0.5f * pt[0].z, 0.5f * pt[1].z));
        const __half2 hx1 = h2_tanh(__floats2half2_rn(0.5f * pt[2].x, 0.5f * pt[3].x));
        const __half2 hy1 = h2_tanh(__floats2half2_rn(0.5f * pt[2].y, 0.5f * pt[3].y));
        const __half2 hz1 = h2_tanh(__floats2half2_rn(0.5f * pt[2].z, 0.5f * pt[3].z));

        float ar = fmaf(w0, __low2float (hx0),
                   fmaf(w1, __high2float(hx0),
                   fmaf(w2, __low2float (hx1), w3 * __high2float(hx1))));
        float ag = fmaf(w0, __low2float (hy0),
                   fmaf(w1, __high2float(hy0),
                   fmaf(w2, __low2float (hy1), w3 * __high2float(hy1))));
        float ab = fmaf(w0, __low2float (hz0),
                   fmaf(w1, __high2float(hz0),
                   fmaf(w2, __low2float (hz1), w3 * __high2float(hz1))));
        float aa = (w0 + w1) + (w2 + w3);
        float ad = fmaf(w0, zloc[0], fmaf(w1, zloc[1], fmaf(w2, zloc[2], w3 * zloc[3])));

        // ---- warp tree-reduce the 5 scalars ----
#pragma unroll
        for (int off = 16; off >= 1; off >>= 1) {
            ar += __shfl_xor_sync(FULL, ar, off);
            ag += __shfl_xor_sync(FULL, ag, off);
            ab += __shfl_xor_sync(FULL, ab, off);
            aa += __shfl_xor_sync(FULL, aa, off);
            ad += __shfl_xor_sync(FULL, ad, off);
        }

        if (lane == 0) {
            // fold sigma = 0.5*tanh + 0.5:  sum(w*sigma) = 0.5*sum(w*t) + 0.5*sum(w)
            ar = fmaf(0.5f, ar, 0.5f * aa);
            ag = fmaf(0.5f, ag, 0.5f * aa);
            ab = fmaf(0.5f, ab, 0.5f * aa);

            const float b0 = bg[0], b1 = bg[1], b2 = bg[2];
            const bool is_bg = (b0 >= 0.f && b0 <= 1.f &&
                                b1 >= 0.f && b1 <= 1.f &&
                                b2 >= 0.f && b2 <= 1.f);
            if (is_bg) {
                const float m = 1.0f - aa;
                ar = fmaf(m, b0, ar);
                ag = fmaf(m, b1, ag);
                ab = fmaf(m, b2, ab);
            }
            out_rgb[ray * 3 + 0] = ar;
            out_rgb[ray * 3 + 1] = ag;
            out_rgb[ray * 3 + 2] = ab;
            out_depth[ray] = ad;
            out_alpha[ray] = aa;

            const float q = ad / aa;
            out_disp[ray] = 1.0f / (fmaxf(q - EPSV, 0.0f) + EPSV);
        }
    }
}

extern "C" void kernel_launch(void* const* d_in, const int* in_sizes, int n_in,
                              void* d_out, int out_size)
{
    const float* raw = (const float*)d_in[0];  // (B,R,P,4)
    const float* zv  = (const float*)d_in[1];  // (B,R,P)
    const float* rd  = (const float*)d_in[2];  // (B,R,3)
    const float* bg  = (const float*)d_in[3];  // (3)

    const int nrays = in_sizes[1] / 128;       // B*R

    float* out       = (float*)d_out;
    float* out_rgb   = out;
    float* out_depth = out + (size_t)nrays * 3;
    float* out_disp  = out + (size_t)nrays * 4;
    float* out_alpha = out + (size_t)nrays * 5;
    float* out_w     = out + (size_t)nrays * 6;

    // persistent: exactly one wave of 148*8 blocks (8 warps each), grid-stride
    int blocks = 148 * 8;
    const int maxblk = (nrays + 7) / 8;
    if (blocks > maxblk) blocks = maxblk;
    nerf_agg_kernel<<<blocks, 256>>>((const float4*)raw, zv, rd, bg,
                                     out_rgb, out_depth, out_disp, out_alpha,
                                     out_w, nrays);
}

// round 7
// speedup vs baseline: 1.0674x; 1.0674x over previous
#include <cuda_runtime.h>
#include <cuda_fp16.h>

// NeRF volume-rendering aggregation — R7.
// Diagnosis: DRAM pinned at ~68% across 4 structurally different kernels ->
// per-warp MLP gap (no loads in flight during each warp's compute phase).
// Fix: depth-2 software pipeline.
//  - raw tile: cp.async.cg global->shared, double-buffered per warp
//    (merges the transpose staging with the load; no register residency)
//  - z4 / ray norm: register-pipelined LDGs issued one ray ahead
// Compute core unchanged from R6 (lane owns 4 pts, one warp scan, f16x2 tanh).

#define FARV 1e10f
#define EPSV 1e-10f
#define FULL 0xffffffffu

__device__ __forceinline__ __half2 h2_tanh(__half2 x) {
    __half2 r;
    asm("tanh.approx.f16x2 %0, %1;" : "=r"(*(unsigned*)&r) : "r"(*(unsigned*)&x));
    return r;
}

// XOR-swizzle byte offset within a 2048B tile (flips bits [5:4] by bits [8:7]):
// conflict-free for both the 16B-stride fill and the 64B-stride float4 read.
__device__ __forceinline__ unsigned swz(unsigned a) {
    return a ^ ((a >> 3) & 0x30u);
}

__device__ __forceinline__ void cpasync16(unsigned dst, const void* src) {
    asm volatile("cp.async.cg.shared.global [%0], [%1], 16;" :: "r"(dst), "l"(src));
}
__device__ __forceinline__ void cpcommit() {
    asm volatile("cp.async.commit_group;");
}
__device__ __forceinline__ void cpwait1() {
    asm volatile("cp.async.wait_group 1;");
}

__global__ __launch_bounds__(256) void nerf_agg_kernel(
    const float4* __restrict__ raw,    // (NR, 128) of float4
    const float*  __restrict__ z,      // (NR, 128)
    const float*  __restrict__ rays_d, // (NR, 3)
    const float*  __restrict__ bg,     // (3)
    float* __restrict__ out_rgb,       // (NR, 3)
    float* __restrict__ out_depth,     // (NR)
    float* __restrict__ out_disp,      // (NR)
    float* __restrict__ out_alpha,     // (NR)
    float* __restrict__ out_w,         // (NR, 128)
    int nrays)
{
    __shared__ __align__(128) char sbuf[8 * 2 * 2048];  // per-warp double buffer

    const int warp = threadIdx.x >> 5;
    const int lane = threadIdx.x & 31;
    char* swp = sbuf + warp * 4096;
    const unsigned swb = (unsigned)__cvta_generic_to_shared(swp);

    const int gw = blockIdx.x * 8 + warp;     // global warp id
    const int W  = gridDim.x * 8;             // total warps (stride)
    if (gw >= nrays) return;                  // warp-uniform

    // ---- prologue: prefetch ray gw into buffer 0; z/norm into registers ----
    {
        const float4* rawr = raw + (size_t)gw * 128;
#pragma unroll
        for (int rr = 0; rr < 4; rr++)
            cpasync16(swb + swz((rr * 32 + lane) * 16u), rawr + rr * 32 + lane);
        cpcommit();
    }
    float4 zc = *(const float4*)(z + (size_t)gw * 128 + lane * 4);
    float nrmc;
    {
        const float a = rays_d[gw * 3 + 0];
        const float b = rays_d[gw * 3 + 1];
        const float c = rays_d[gw * 3 + 2];
        nrmc = sqrtf(a * a + b * b + c * c);
    }

    int buf = 0;
    for (int ray = gw; ray < nrays; ray += W) {
        // ---- prefetch next ray (flies during this ray's compute) ----
        const int nray = ray + W;
        float4 zn_c = zc;           // defaults keep compiler happy on tail iter
        float  nrmn = nrmc;
        if (nray < nrays) {         // warp-uniform branch
            const float4* rawr = raw + (size_t)nray * 128;
            const unsigned d = swb + (unsigned)(buf ^ 1) * 2048u;
#pragma unroll
            for (int rr = 0; rr < 4; rr++)
                cpasync16(d + swz((rr * 32 + lane) * 16u), rawr + rr * 32 + lane);
            zn_c = *(const float4*)(z + (size_t)nray * 128 + lane * 4);
            const float a = rays_d[nray * 3 + 0];
            const float b = rays_d[nray * 3 + 1];
            const float c = rays_d[nray * 3 + 2];
            nrmn = sqrtf(a * a + b * b + c * c);
        }
        cpcommit();                 // one group per iteration (may be empty)
        cpwait1();                  // current buffer's group complete
        __syncwarp();

        // ---- read transposed points from smem ----
        char* d = swp + buf * 2048;
        float4 pt[4];
#pragma unroll
        for (int i = 0; i < 4; i++)
            pt[i] = *(const float4*)(d + swz((lane * 4 + i) * 16u));

        const float4 z4 = zc;
        const float  nrm = nrmc;

        // ---- z neighbors: lane-local except the lane boundary ----
        const float zb = __shfl_down_sync(FULL, z4.x, 1);    // z[lane*4+4]
        const float zloc[4] = { z4.x, z4.y, z4.z, z4.w };
        const float znxt[4] = { z4.y, z4.z, z4.w, zb };

        // ---- alpha + transmittance factors (f32 EX2) ----
        float alpha[4], t[4];
#pragma unroll
        for (int i = 0; i < 4; i++) {
            float dd = znxt[i] - zloc[i];
            if (i == 3 && lane == 31) dd = FARV;             // p == 127
            dd *= nrm;
            const float ex = __expf(-fmaxf(pt[i].w, 0.0f) * dd);
            alpha[i] = 1.0f - ex;
            t[i]     = ex + EPSV;                            // 1 - alpha + EPS
        }

        // ---- single warp scan over local products ----
        float S = (t[0] * t[1]) * (t[2] * t[3]);
#pragma unroll
        for (int off = 1; off < 32; off <<= 1) {
            const float v = __shfl_up_sync(FULL, S, off);
            S = (lane >= off) ? S * v : S;
        }
        float E = __shfl_up_sync(FULL, S, 1);                // exclusive lane prefix
        if (lane == 0) E = 1.0f;

        const float e1 = E  * t[0];
        const float e2 = e1 * t[1];
        const float e3 = e2 * t[2];
        const float w0 = alpha[0] * E;
        const float w1 = alpha[1] * e1;
        const float w2 = alpha[2] * e2;
        const float w3 = alpha[3] * e3;

        *(float4*)(out_w + (size_t)ray * 128 + lane * 4) = make_float4(w0, w1, w2, w3);

        // ---- packed tanh; accumulate raw tanh dot-products ----
        const __half2 hx0 = h2_tanh(__floats2half2_rn(0.5f * pt[0].x, 0.5f * pt[1].x));
        const __half2 hy0 = h2_tanh(__floats2half2_rn(0.5f * pt[0].y, 0.5f * pt[1].y));
        const __half2 hz0 = h2_tanh(__floats2half2_rn(0.5f * pt[0].z, 0.5f * pt[1].z));
        const __half2 hx1 = h2_tanh(__floats2half2_rn(0.5f * pt[2].x, 0.5f * pt[3].x));
        const __half2 hy1 = h2_tanh(__floats2half2_rn(0.5f * pt[2].y, 0.5f * pt[3].y));
        const __half2 hz1 = h2_tanh(__floats2half2_rn(0.5f * pt[2].z, 0.5f * pt[3].z));

        float ar = fmaf(w0, __low2float (hx0),
                   fmaf(w1, __high2float(hx0),
                   fmaf(w2, __low2float (hx1), w3 * __high2float(hx1))));
        float ag = fmaf(w0, __low2float (hy0),
                   fmaf(w1, __high2float(hy0),
                   fmaf(w2, __low2float (hy1), w3 * __high2float(hy1))));
        float ab = fmaf(w0, __low2float (hz0),
                   fmaf(w1, __high2float(hz0),
                   fmaf(w2, __low2float (hz1), w3 * __high2float(hz1))));
        float aa = (w0 + w1) + (w2 + w3);
        float ad = fmaf(w0, zloc[0], fmaf(w1, zloc[1], fmaf(w2, zloc[2], w3 * zloc[3])));

        // ---- warp tree-reduce the 5 scalars ----
#pragma unroll
        for (int off = 16; off >= 1; off >>= 1) {
            ar += __shfl_xor_sync(FULL, ar, off);
            ag += __shfl_xor_sync(FULL, ag, off);
            ab += __shfl_xor_sync(FULL, ab, off);
            aa += __shfl_xor_sync(FULL, aa, off);
            ad += __shfl_xor_sync(FULL, ad, off);
        }

        if (lane == 0) {
            // fold sigma = 0.5*tanh + 0.5
            ar = fmaf(0.5f, ar, 0.5f * aa);
            ag = fmaf(0.5f, ag, 0.5f * aa);
            ab = fmaf(0.5f, ab, 0.5f * aa);

            const float b0 = bg[0], b1 = bg[1], b2 = bg[2];
            const bool is_bg = (b0 >= 0.f && b0 <= 1.f &&
                                b1 >= 0.f && b1 <= 1.f &&
                                b2 >= 0.f && b2 <= 1.f);
            if (is_bg) {
                const float m = 1.0f - aa;
                ar = fmaf(m, b0, ar);
                ag = fmaf(m, b1, ag);
                ab = fmaf(m, b2, ab);
            }
            out_rgb[ray * 3 + 0] = ar;
            out_rgb[ray * 3 + 1] = ag;
            out_rgb[ray * 3 + 2] = ab;
            out_depth[ray] = ad;
            out_alpha[ray] = aa;

            const float q = ad / aa;
            out_disp[ray] = 1.0f / (fmaxf(q - EPSV, 0.0f) + EPSV);
        }

        // ---- rotate pipeline ----
        zc   = zn_c;
        nrmc = nrmn;
        buf ^= 1;
    }
}

extern "C" void kernel_launch(void* const* d_in, const int* in_sizes, int n_in,
                              void* d_out, int out_size)
{
    const float* raw = (const float*)d_in[0];  // (B,R,P,4)
    const float* zv  = (const float*)d_in[1];  // (B,R,P)
    const float* rd  = (const float*)d_in[2];  // (B,R,3)
    const float* bg  = (const float*)d_in[3];  // (3)

    const int nrays = in_sizes[1] / 128;       // B*R

    float* out       = (float*)d_out;
    float* out_rgb   = out;
    float* out_depth = out + (size_t)nrays * 3;
    float* out_disp  = out + (size_t)nrays * 4;
    float* out_alpha = out + (size_t)nrays * 5;
    float* out_w     = out + (size_t)nrays * 6;

    int blocks = 148 * 8;
    const int maxblk = (nrays + 7) / 8;
    if (blocks > maxblk) blocks = maxblk;
    nerf_agg_kernel<<<blocks, 256>>>((const float4*)raw, zv, rd, bg,
                                     out_rgb, out_depth, out_disp, out_alpha,
                                     out_w, nrays);
}